// round 7
// baseline (speedup 1.0000x reference)
#include <cuda_runtime.h>
#include <cstdint>
#include <math.h>

// Problem dims
#define BB 64
#define TT 4096
#define HH 256
#define II 7
#define XD 12   // I + F

#define NRNN 32              // RNN CTAs, 2 chains each
#define NWORK 116
#define NCTA (NRNN + NWORK)  // 148
#define NT2 256

// ---------------- device scratch ----------------------------------------------
__device__ float g_ht[(size_t)BB * TT * HH];   // RNN hidden states (256 MB)
__device__ float g_xw[(size_t)BB * TT * HH];   // precomputed xW + biases (256 MB)
__device__ float g_wt[110520];                 // transposed MLP weights
__device__ int   g_prog[BB];                   // RNN progress per chain
__device__ int   g_tick;                       // MLP chunk ticket counter

// MLP layer offsets in g_wt
#define OFF0 0
#define OFF1 66816
#define OFF2 99584
#define OFF3 107776
#define OFF4 109824
#define OFF5 110336
#define OFF6 110464

// ---------------- helpers ------------------------------------------------------
__device__ __forceinline__ unsigned long long fma2(unsigned long long a,
                                                   unsigned long long b,
                                                   unsigned long long c) {
    unsigned long long d;
    asm("fma.rn.f32x2 %0, %1, %2, %3;" : "=l"(d) : "l"(a), "l"(b), "l"(c));
    return d;
}
__device__ __forceinline__ unsigned long long pack2(float lo, float hi) {
    unsigned long long d;
    asm("mov.b64 %0, {%1, %2};" : "=l"(d) : "f"(lo), "f"(hi));
    return d;
}
__device__ __forceinline__ float2 unpack2(unsigned long long v) {
    float lo, hi;
    asm("mov.b64 {%0, %1}, %2;" : "=f"(lo), "=f"(hi) : "l"(v));
    return make_float2(lo, hi);
}
__device__ __forceinline__ float rsum4(unsigned long long A, unsigned long long B) {
    float2 a = unpack2(A), b = unpack2(B);
    return (a.x + a.y) + (b.x + b.y);
}
__device__ __forceinline__ int ld_acquire(const int* p) {
    int v;
    asm volatile("ld.global.acquire.gpu.b32 %0, [%1];" : "=r"(v) : "l"(p));
    return v;
}
__device__ __forceinline__ void st_release(int* p, int v) {
    asm volatile("st.global.release.gpu.b32 [%0], %1;" :: "l"(p), "r"(v));
}
__device__ __forceinline__ float fast_tanh(float x) {
    float e = __expf(2.0f * x);
    return 1.0f - __fdividef(2.0f, e + 1.0f);
}
__device__ __forceinline__ void cpa16(uint32_t s, const void* g) {
    asm volatile("cp.async.cg.shared.global [%0], [%1], 16;" :: "r"(s), "l"(g));
}
__device__ __forceinline__ void cpa_commit() {
    asm volatile("cp.async.commit_group;" ::: "memory");
}

// ---------------- RNN config ---------------------------------------------------
// 256 threads/CTA, TWO chains per CTA. warp w, lane: q = lane>>3, r = lane&7.
// Thread: rows j0..j0+3 (j0 = w*32 + r*4), k in [q*64, q*64+64), both chains.
// Per row: 48 weight floats in regs (96 ull total for 4 rows), 16 in smem.
#define RWP 48
#define SWP 16
#define WTST 68       // per-thread smem weight stride (64 used + 4 pad)
#define HQ 68         // h quarter stride
#define HBF 272       // h buffer stride (4*HQ)
#define CH 16         // xw chunk (steps)
#define NCH (TT / CH) // 256

// smem: weights 256*68=17408 | xw 2 chains*2 bufs*CH*HH=16384 | h 4*HBF=1088
#define RNN_SMF (NT2 * WTST + 4 * CH * HH + 4 * HBF)   // 34880 floats = 139520 B

// ---------------- MLP config ---------------------------------------------------
#define TOKN 64
#define TOKP 68
#define MLP_SMF ((264 + 256) * TOKP)                   // 35360 floats = 141440 B
#define FUSED_SMEM_B (MLP_SMF * 4)

template<int DOUT, int DIN, int TPG, bool LEAKY>
__device__ __forceinline__ void mlp_layer(const float* __restrict__ zin,
                                          float* __restrict__ zout,
                                          const float* __restrict__ wt,
                                          const float* __restrict__ bias)
{
    const int tid = threadIdx.x;
    const int o = tid % DOUT;
    const int g = tid / DOUT;

    if constexpr (TPG >= 4) {
        constexpr int NP = TPG / 2;
        unsigned long long acc[NP];
        #pragma unroll
        for (int p = 0; p < NP; p++) acc[p] = pack2(0.0f, 0.0f);
        #pragma unroll 4
        for (int k = 0; k < DIN; k++) {
            const float w = wt[k * DOUT + o];
            const unsigned long long w2 = pack2(w, w);
            const ulonglong2* zr = (const ulonglong2*)(zin + k * TOKP + g * TPG);
            #pragma unroll
            for (int p = 0; p < TPG / 4; p++) {
                ulonglong2 u = zr[p];
                acc[2 * p]     = fma2(w2, u.x, acc[2 * p]);
                acc[2 * p + 1] = fma2(w2, u.y, acc[2 * p + 1]);
            }
        }
        const float bv = bias[o];
        float* orow = zout + o * TOKP + g * TPG;
        #pragma unroll
        for (int p = 0; p < NP; p++) {
            float2 v = unpack2(acc[p]);
            v.x += bv; v.y += bv;
            if (LEAKY) { v.x = fmaxf(v.x, 0.01f * v.x); v.y = fmaxf(v.y, 0.01f * v.y); }
            orow[2 * p] = v.x; orow[2 * p + 1] = v.y;
        }
    } else if constexpr (TPG == 2) {
        unsigned long long acc = pack2(0.0f, 0.0f);
        #pragma unroll 4
        for (int k = 0; k < DIN; k++) {
            const float w = wt[k * DOUT + o];
            unsigned long long u = *(const unsigned long long*)(zin + k * TOKP + g * 2);
            acc = fma2(pack2(w, w), u, acc);
        }
        const float bv = bias[o];
        float2 v = unpack2(acc);
        v.x += bv; v.y += bv;
        if (LEAKY) { v.x = fmaxf(v.x, 0.01f * v.x); v.y = fmaxf(v.y, 0.01f * v.y); }
        float* orow = zout + o * TOKP + g * 2;
        orow[0] = v.x; orow[1] = v.y;
    }
}

// ---------------- RNN side: two chains per CTA ---------------------------------
__device__ void rnn_cta(const float* __restrict__ W_hh, float* __restrict__ out,
                        float* sm, int cta)
{
    float* ws  = sm;                          // NT2*WTST
    float* xws = sm + NT2 * WTST;             // [chain][buf][CH*HH]
    float* hb  = xws + 4 * CH * HH;           // [chain][buf][HBF]
    const int b0 = 2 * cta, b1 = 2 * cta + 1;
    const int tid = threadIdx.x;
    const int w = tid >> 5, lane = tid & 31;
    const int q = lane >> 3, r = lane & 7;
    const int j0 = w * 32 + r * 4;
    const int myrow = j0 + q;
    const int hoff = (myrow >> 6) * HQ + (myrow & 63);

    // register weights: 4 rows x 48 floats (shared by both chains)
    unsigned long long w0[RWP / 2], w1[RWP / 2], w2[RWP / 2], w3[RWP / 2];
    {
        const ulonglong2* p0 = (const ulonglong2*)(W_hh + (j0 + 0) * HH + q * 64);
        const ulonglong2* p1 = (const ulonglong2*)(W_hh + (j0 + 1) * HH + q * 64);
        const ulonglong2* p2 = (const ulonglong2*)(W_hh + (j0 + 2) * HH + q * 64);
        const ulonglong2* p3 = (const ulonglong2*)(W_hh + (j0 + 3) * HH + q * 64);
        #pragma unroll
        for (int i = 0; i < RWP / 4; i++) {
            ulonglong2 u;
            u = p0[i]; w0[2 * i] = u.x; w0[2 * i + 1] = u.y;
            u = p1[i]; w1[2 * i] = u.x; w1[2 * i + 1] = u.y;
            u = p2[i]; w2[2 * i] = u.x; w2[2 * i + 1] = u.y;
            u = p3[i]; w3[2 * i] = u.x; w3[2 * i + 1] = u.y;
        }
    }
    // smem weights: 4 rows x 16 floats
    #pragma unroll
    for (int rr = 0; rr < 4; rr++) {
        const float4* gsrc = (const float4*)(W_hh + (j0 + rr) * HH + q * 64 + RWP);
        float4* dst = (float4*)(ws + tid * WTST + rr * SWP);
        #pragma unroll
        for (int i = 0; i < SWP / 4; i++) dst[i] = gsrc[i];
    }

    for (int idx = tid; idx < 4 * HBF; idx += NT2) hb[idx] = 0.0f;

    const float* xgA = g_xw + (size_t)b0 * TT * HH;
    const float* xgB = g_xw + (size_t)b1 * TT * HH;
    float* houtA = g_ht + (size_t)b0 * TT * HH;
    float* houtB = g_ht + (size_t)b1 * TT * HH;
    const uint32_t xw_sbase = (uint32_t)__cvta_generic_to_shared(xws);
    // xws float offsets: chain*2*CH*HH + buf*CH*HH
    #define XWO(chain, buf) ((uint32_t)(((chain) * 2 + (buf)) * CH * HH))

    // prologue: stage chunk 0 and 1 for both chains (CH*HH = 4096 floats = 1024 f4)
    #pragma unroll
    for (int i = 0; i < 4; i++) {
        cpa16(xw_sbase + (XWO(0, 0) / 4 + tid + i * NT2) * 16,
              (const float4*)xgA + tid + i * NT2);
        cpa16(xw_sbase + (XWO(1, 0) / 4 + tid + i * NT2) * 16,
              (const float4*)xgB + tid + i * NT2);
    }
    cpa_commit();
    #pragma unroll
    for (int i = 0; i < 4; i++) {
        cpa16(xw_sbase + (XWO(0, 1) / 4 + tid + i * NT2) * 16,
              (const float4*)(xgA + CH * HH) + tid + i * NT2);
        cpa16(xw_sbase + (XWO(1, 1) / 4 + tid + i * NT2) * 16,
              (const float4*)(xgB + CH * HH) + tid + i * NT2);
    }
    cpa_commit();

    int buf = 0;
    float hlA = 0.0f, hlB = 0.0f;
    const ulonglong2* swp = (const ulonglong2*)(ws + tid * WTST);
    float* hbA = hb;
    float* hbB = hb + 2 * HBF;

    for (int c = 0; c < NCH; c++) {
        if (c >= NCH - 2) { asm volatile("cp.async.wait_group 0;" ::: "memory"); }
        else              { asm volatile("cp.async.wait_group 1;" ::: "memory"); }
        __syncthreads();
        const float* xwcA = xws + XWO(0, c & 1);
        const float* xwcB = xws + XWO(1, c & 1);

        for (int s = 0; s < CH; s++) {
            const float xwA = xwcA[s * HH + myrow];
            const float xwB = xwcB[s * HH + myrow];

            const ulonglong2* hA2 = (const ulonglong2*)(hbA + buf * HBF + q * HQ);
            const ulonglong2* hB2 = (const ulonglong2*)(hbB + buf * HBF + q * HQ);

            unsigned long long aA0 = pack2(0.f, 0.f), aA1 = aA0, aA2 = aA0, aA3 = aA0;
            unsigned long long aA4 = aA0, aA5 = aA0, aA6 = aA0, aA7 = aA0;
            unsigned long long aB0 = aA0, aB1 = aA0, aB2 = aA0, aB3 = aA0;
            unsigned long long aB4 = aA0, aB5 = aA0, aB6 = aA0, aB7 = aA0;

            #pragma unroll
            for (int i = 0; i < RWP / 4; i++) {          // k_rel 0..47 (regs)
                ulonglong2 uA = hA2[i];
                ulonglong2 uB = hB2[i];
                aA0 = fma2(w0[2 * i],     uA.x, aA0);
                aA1 = fma2(w0[2 * i + 1], uA.y, aA1);
                aA2 = fma2(w1[2 * i],     uA.x, aA2);
                aA3 = fma2(w1[2 * i + 1], uA.y, aA3);
                aA4 = fma2(w2[2 * i],     uA.x, aA4);
                aA5 = fma2(w2[2 * i + 1], uA.y, aA5);
                aA6 = fma2(w3[2 * i],     uA.x, aA6);
                aA7 = fma2(w3[2 * i + 1], uA.y, aA7);
                aB0 = fma2(w0[2 * i],     uB.x, aB0);
                aB1 = fma2(w0[2 * i + 1], uB.y, aB1);
                aB2 = fma2(w1[2 * i],     uB.x, aB2);
                aB3 = fma2(w1[2 * i + 1], uB.y, aB3);
                aB4 = fma2(w2[2 * i],     uB.x, aB4);
                aB5 = fma2(w2[2 * i + 1], uB.y, aB5);
                aB6 = fma2(w3[2 * i],     uB.x, aB6);
                aB7 = fma2(w3[2 * i + 1], uB.y, aB7);
            }
            #pragma unroll
            for (int i = 0; i < SWP / 4; i++) {          // k_rel 48..63 (smem)
                ulonglong2 uA = hA2[RWP / 4 + i];
                ulonglong2 uB = hB2[RWP / 4 + i];
                ulonglong2 v0 = swp[0 + i];
                ulonglong2 v1 = swp[SWP / 4 + i];
                ulonglong2 v2 = swp[2 * (SWP / 4) + i];
                ulonglong2 v3 = swp[3 * (SWP / 4) + i];
                aA0 = fma2(v0.x, uA.x, aA0);
                aA1 = fma2(v0.y, uA.y, aA1);
                aA2 = fma2(v1.x, uA.x, aA2);
                aA3 = fma2(v1.y, uA.y, aA3);
                aA4 = fma2(v2.x, uA.x, aA4);
                aA5 = fma2(v2.y, uA.y, aA5);
                aA6 = fma2(v3.x, uA.x, aA6);
                aA7 = fma2(v3.y, uA.y, aA7);
                aB0 = fma2(v0.x, uB.x, aB0);
                aB1 = fma2(v0.y, uB.y, aB1);
                aB2 = fma2(v1.x, uB.x, aB2);
                aB3 = fma2(v1.y, uB.y, aB3);
                aB4 = fma2(v2.x, uB.x, aB4);
                aB5 = fma2(v2.y, uB.y, aB5);
                aB6 = fma2(v3.x, uB.x, aB6);
                aB7 = fma2(v3.y, uB.y, aB7);
            }

            float pA0 = rsum4(aA0, aA1), pA1 = rsum4(aA2, aA3);
            float pA2 = rsum4(aA4, aA5), pA3 = rsum4(aA6, aA7);
            float pB0 = rsum4(aB0, aB1), pB1 = rsum4(aB2, aB3);
            float pB2 = rsum4(aB4, aB5), pB3 = rsum4(aB6, aB7);
            pA0 += __shfl_xor_sync(0xFFFFFFFFu, pA0, 8);
            pA1 += __shfl_xor_sync(0xFFFFFFFFu, pA1, 8);
            pA2 += __shfl_xor_sync(0xFFFFFFFFu, pA2, 8);
            pA3 += __shfl_xor_sync(0xFFFFFFFFu, pA3, 8);
            pB0 += __shfl_xor_sync(0xFFFFFFFFu, pB0, 8);
            pB1 += __shfl_xor_sync(0xFFFFFFFFu, pB1, 8);
            pB2 += __shfl_xor_sync(0xFFFFFFFFu, pB2, 8);
            pB3 += __shfl_xor_sync(0xFFFFFFFFu, pB3, 8);
            pA0 += __shfl_xor_sync(0xFFFFFFFFu, pA0, 16);
            pA1 += __shfl_xor_sync(0xFFFFFFFFu, pA1, 16);
            pA2 += __shfl_xor_sync(0xFFFFFFFFu, pA2, 16);
            pA3 += __shfl_xor_sync(0xFFFFFFFFu, pA3, 16);
            pB0 += __shfl_xor_sync(0xFFFFFFFFu, pB0, 16);
            pB1 += __shfl_xor_sync(0xFFFFFFFFu, pB1, 16);
            pB2 += __shfl_xor_sync(0xFFFFFFFFu, pB2, 16);
            pB3 += __shfl_xor_sync(0xFFFFFFFFu, pB3, 16);

            const float sdA = (q == 0) ? pA0 : (q == 1) ? pA1 : (q == 2) ? pA2 : pA3;
            const float sdB = (q == 0) ? pB0 : (q == 1) ? pB1 : (q == 2) ? pB2 : pB3;
            const float hnA = fast_tanh(sdA + xwA);
            const float hnB = fast_tanh(sdB + xwB);

            hbA[(buf ^ 1) * HBF + hoff] = hnA;
            hbB[(buf ^ 1) * HBF + hoff] = hnB;
            const size_t t = (size_t)(c * CH + s);
            houtA[t * HH + myrow] = hnA;
            houtB[t * HH + myrow] = hnB;
            hlA = hnA; hlB = hnB;
            __syncthreads();
            buf ^= 1;
        }

        if (tid == 0) st_release(&g_prog[b0], (c + 1) * CH);
        if (tid == 1) st_release(&g_prog[b1], (c + 1) * CH);

        if (c + 2 < NCH) {
            const float4* gA = (const float4*)(xgA + (size_t)(c + 2) * CH * HH);
            const float4* gB = (const float4*)(xgB + (size_t)(c + 2) * CH * HH);
            const uint32_t sbA = xw_sbase + XWO(0, c & 1) * 4;
            const uint32_t sbB = xw_sbase + XWO(1, c & 1) * 4;
            #pragma unroll
            for (int i = 0; i < 4; i++) {
                cpa16(sbA + (uint32_t)(tid + i * NT2) * 16, gA + tid + i * NT2);
                cpa16(sbB + (uint32_t)(tid + i * NT2) * 16, gB + tid + i * NT2);
            }
            cpa_commit();
        }
    }
    out[(size_t)BB * TT * II + (size_t)b0 * HH + myrow] = hlA;
    out[(size_t)BB * TT * II + (size_t)b1 * HH + myrow] = hlB;
    asm volatile("cp.async.wait_group 0;" ::: "memory");
    __syncthreads();
    #undef XWO
}

// ---------------- MLP worker ----------------------------------------------------
__device__ void mlp_worker(
    const float* __restrict__ x,
    const float* __restrict__ b0, const float* __restrict__ b1,
    const float* __restrict__ b2, const float* __restrict__ b3,
    const float* __restrict__ b4, const float* __restrict__ b5,
    const float* __restrict__ b6, float* __restrict__ out,
    float* sm)
{
    __shared__ int s_blk;
    float* bufA = sm;
    float* bufB = sm + 264 * TOKP;
    const int tid = threadIdx.x;

    for (;;) {
        __syncthreads();
        if (tid == 0) s_blk = atomicAdd(&g_tick, 1);
        __syncthreads();
        const int blk = s_blk;
        if (blk >= 64 * BB) return;
        const int tc = blk >> 6;       // chunk of 64 steps
        const int b = blk & 63;        // chain
        const int need = (tc + 1) * 64;

        if (tid == 0) {
            while (ld_acquire(&g_prog[b]) < need) __nanosleep(128);
        }
        __syncthreads();

        const size_t tok0 = (size_t)b * TT + (size_t)tc * TOKN;

        for (int idx = tid; idx < TOKN * 256; idx += NT2) {
            const int tk = idx >> 8, jj = idx & 255;
            bufA[jj * TOKP + tk] = g_ht[(tok0 + tk) * HH + jj];
        }
        for (int idx = tid; idx < TOKN * 5; idx += NT2) {
            const int tk = idx / 5, i = idx - tk * 5;
            bufA[(256 + i) * TOKP + tk] = x[(tok0 + tk) * XD + II + i];
        }
        __syncthreads();

        mlp_layer<256, 261, 64, true>(bufA, bufB, g_wt + OFF0, b0); __syncthreads();
        mlp_layer<128, 256, 32, true>(bufB, bufA, g_wt + OFF1, b1); __syncthreads();
        mlp_layer< 64, 128, 16, true>(bufA, bufB, g_wt + OFF2, b2); __syncthreads();
        mlp_layer< 32,  64,  8, true>(bufB, bufA, g_wt + OFF3, b3); __syncthreads();
        mlp_layer< 16,  32,  4, true>(bufA, bufB, g_wt + OFF4, b4); __syncthreads();
        mlp_layer<  8,  16,  2, true>(bufB, bufA, g_wt + OFF5, b5); __syncthreads();

        {
            const int o = tid & 7, g0 = tid >> 3;   // g0 in [0,32)
            if (o < 7) {
                #pragma unroll
                for (int g = g0; g < TOKN; g += 32) {
                    float acc = b6[o];
                    #pragma unroll
                    for (int k = 0; k < 8; k++)
                        acc = fmaf(g_wt[OFF6 + k * 7 + o], bufA[k * TOKP + g], acc);
                    out[(tok0 + g) * II + o] = acc;
                }
            }
        }
    }
}

// ---------------- fused kernel --------------------------------------------------
__global__ __launch_bounds__(NT2, 1) void fused_kernel(
    const float* __restrict__ x, const float* __restrict__ W_hh,
    const float* __restrict__ b0, const float* __restrict__ b1,
    const float* __restrict__ b2, const float* __restrict__ b3,
    const float* __restrict__ b4, const float* __restrict__ b5,
    const float* __restrict__ b6, float* __restrict__ out)
{
    extern __shared__ float sm[];
    if (blockIdx.x < NRNN) {
        rnn_cta(W_hh, out, sm, blockIdx.x);
        // chains finished -> join the MLP pool on this SM
        mlp_worker(x, b0, b1, b2, b3, b4, b5, b6, out, sm);
    } else {
        mlp_worker(x, b0, b1, b2, b3, b4, b5, b6, out, sm);
    }
}

// ---------------- xW precompute -------------------------------------------------
__global__ void xw_kernel(const float* __restrict__ x, const float* __restrict__ W_ih,
                          const float* __restrict__ b_ih, const float* __restrict__ b_hh)
{
    const int stride = gridDim.x * blockDim.x;
    for (size_t idx = (size_t)blockIdx.x * blockDim.x + threadIdx.x;
         idx < (size_t)BB * TT * HH; idx += stride) {
        const size_t tok = idx >> 8;
        const int j = (int)(idx & 255);
        const float* xr = x + tok * XD;
        float acc = b_ih[j] + b_hh[j];
        #pragma unroll
        for (int i = 0; i < II; i++) acc = fmaf(xr[i], W_ih[j * II + i], acc);
        g_xw[idx] = acc;
    }
}

// ---------------- prep ----------------------------------------------------------
__global__ void prep_kernel(const float* __restrict__ W0, const float* __restrict__ W1,
                            const float* __restrict__ W2, const float* __restrict__ W3,
                            const float* __restrict__ W4, const float* __restrict__ W5,
                            const float* __restrict__ W6)
{
    if (blockIdx.x == 0) {
        if (threadIdx.x < BB) g_prog[threadIdx.x] = 0;
        if (threadIdx.x == 0) g_tick = 0;
    }
    const float* Ws[7] = {W0, W1, W2, W3, W4, W5, W6};
    const int douts[7] = {256, 128, 64, 32, 16, 8, 7};
    const int dins[7]  = {261, 256, 128, 64, 32, 16, 8};
    int off = 0;
    const int stride = gridDim.x * blockDim.x;
    const int tid0 = blockIdx.x * blockDim.x + threadIdx.x;
    for (int l = 0; l < 7; l++) {
        const int dout = douts[l], din = dins[l], n = dout * din;
        const float* W = Ws[l];
        for (int idx = tid0; idx < n; idx += stride) {
            const int k = idx / dout, o = idx - k * dout;
            g_wt[off + idx] = W[o * din + k];
        }
        off += n;
    }
}

// ---------------- launch --------------------------------------------------------
extern "C" void kernel_launch(void* const* d_in, const int* in_sizes, int n_in,
                              void* d_out, int out_size)
{
    const float* x    = (const float*)d_in[0];
    const float* W_ih = (const float*)d_in[1];
    const float* W_hh = (const float*)d_in[2];
    const float* b_ih = (const float*)d_in[3];
    const float* b_hh = (const float*)d_in[4];
    const float* W[7];
    const float* bb[7];
    for (int i = 0; i < 7; i++) {
        W[i]  = (const float*)d_in[5 + 2 * i];
        bb[i] = (const float*)d_in[6 + 2 * i];
    }
    float* out = (float*)d_out;

    static int inited = 0;
    if (!inited) {
        cudaFuncSetAttribute(fused_kernel,
                             cudaFuncAttributeMaxDynamicSharedMemorySize, FUSED_SMEM_B);
        inited = 1;
    }

    prep_kernel<<<64, 256>>>(W[0], W[1], W[2], W[3], W[4], W[5], W[6]);
    xw_kernel<<<512, 256>>>(x, W_ih, b_ih, b_hh);
    fused_kernel<<<NCTA, NT2, FUSED_SMEM_B>>>(x, W_hh,
                                              bb[0], bb[1], bb[2], bb[3],
                                              bb[4], bb[5], bb[6], out);
}